// round 9
// baseline (speedup 1.0000x reference)
#include <cuda_runtime.h>

#define N_NODES 50000
#define N_EDGES 800000
#define D 64
#define SCAN_B 256
#define SCAN_NBLK ((N_NODES + SCAN_B - 1) / SCAN_B)   // 196
#define MEAN_SPREAD 8
#define NPB 64
#define LAYER_GRID ((N_NODES + NPB - 1) / NPB)        // 782
#define RSTRIDE 68

__device__ float g_ha[N_NODES * D];
__device__ float g_hb[N_NODES * D];
__device__ float g_dinv[N_NODES];
__device__ int   g_cnt [N_NODES];
__device__ int   g_cur [N_NODES];
__device__ int   g_rowptr[N_NODES];
__device__ int   g_blocksum[SCAN_NBLK];
__device__ int2  g_csr[N_EDGES];
__device__ float g_meanacc[4 * MEAN_SPREAD * D];
__device__ int   g_is64;

__global__ void k_detect(const int* __restrict__ ei32) {
    __shared__ int bad;
    if (threadIdx.x == 0) bad = 0;
    __syncthreads();
    for (int t = threadIdx.x; t < 1024; t += blockDim.x)
        if (ei32[2 * t + 1] != 0) bad = 1;
    __syncthreads();
    if (threadIdx.x == 0) g_is64 = bad ? 0 : 1;
}

__device__ __forceinline__ int load_idx(const void* ei, int pos) {
    int v = g_is64 ? (int)((const long long*)ei)[pos] : ((const int*)ei)[pos];
    return min(max(v, 0), N_NODES - 1);
}

__global__ void k_hist(const void* __restrict__ ei) {
    int e = blockIdx.x * blockDim.x + threadIdx.x;
    if (e < N_EDGES) atomicAdd(&g_cnt[load_idx(ei, N_EDGES + e)], 1);
}

__global__ void k_scan1() {
    __shared__ int sh[SCAN_B];
    int b = blockIdx.x, t = threadIdx.x;
    int i = b * SCAN_B + t;
    int v = (i < N_NODES) ? g_cnt[i] : 0;
    sh[t] = v;
    __syncthreads();
    for (int off = 1; off < SCAN_B; off <<= 1) {
        int add = (t >= off) ? sh[t - off] : 0;
        __syncthreads();
        sh[t] += add;
        __syncthreads();
    }
    if (i < N_NODES) {
        g_rowptr[i] = sh[t] - v;
        g_dinv[i]   = rsqrtf(1.0f + (float)v);
    }
    if (t == SCAN_B - 1) g_blocksum[b] = sh[t];
}

__global__ void k_scan2() {
    __shared__ int sh[SCAN_B];
    int t = threadIdx.x;
    int v = (t < SCAN_NBLK) ? g_blocksum[t] : 0;
    sh[t] = v;
    __syncthreads();
    for (int off = 1; off < SCAN_B; off <<= 1) {
        int add = (t >= off) ? sh[t - off] : 0;
        __syncthreads();
        sh[t] += add;
        __syncthreads();
    }
    if (t < SCAN_NBLK) g_blocksum[t] = sh[t] - v;
}

__global__ void k_fill(const void* __restrict__ ei) {
    int e = blockIdx.x * blockDim.x + threadIdx.x;
    if (e >= N_EDGES) return;
    int s = load_idx(ei, e);
    int d = load_idx(ei, N_EDGES + e);
    int pos = g_rowptr[d] + g_blocksum[d >> 8] + atomicAdd(&g_cur[d], 1);
    g_csr[pos] = make_int2(s, __float_as_int(g_dinv[s] * g_dinv[d]));
}

__global__ void k_gemm0(const float* __restrict__ xin, const float* __restrict__ W) {
    __shared__ float Ws[64 * 64];
    __shared__ float xs[64 * 64];

    int tid = threadIdx.x;
    const float4* W4 = (const float4*)W;
    float4* Ws4 = (float4*)Ws;
    #pragma unroll
    for (int i = tid; i < 1024; i += 256) Ws4[i] = W4[i];

    int row0 = blockIdx.x * 64;
    const float4* x4 = (const float4*)xin;
    float4* xs4 = (float4*)xs;
    #pragma unroll
    for (int i = tid; i < 1024; i += 256) {
        int r = row0 + (i >> 4);
        xs4[i] = (r < N_NODES) ? x4[r * 16 + (i & 15)]
                               : make_float4(0.f, 0.f, 0.f, 0.f);
    }
    __syncthreads();

    int jc = (tid & 15) * 4;
    int rc = (tid >> 4) * 4;
    float4 acc[4];
    #pragma unroll
    for (int r = 0; r < 4; r++) acc[r] = make_float4(0.f, 0.f, 0.f, 0.f);

    #pragma unroll
    for (int k4 = 0; k4 < 16; k4++) {
        float4 wv[4];
        #pragma unroll
        for (int kk = 0; kk < 4; kk++)
            wv[kk] = *(const float4*)&Ws[(k4 * 4 + kk) * 64 + jc];
        #pragma unroll
        for (int r = 0; r < 4; r++) {
            float4 a = *(const float4*)&xs[(rc + r) * 64 + k4 * 4];
            acc[r].x = fmaf(a.x, wv[0].x, acc[r].x);
            acc[r].y = fmaf(a.x, wv[0].y, acc[r].y);
            acc[r].z = fmaf(a.x, wv[0].z, acc[r].z);
            acc[r].w = fmaf(a.x, wv[0].w, acc[r].w);
            acc[r].x = fmaf(a.y, wv[1].x, acc[r].x);
            acc[r].y = fmaf(a.y, wv[1].y, acc[r].y);
            acc[r].z = fmaf(a.y, wv[1].z, acc[r].z);
            acc[r].w = fmaf(a.y, wv[1].w, acc[r].w);
            acc[r].x = fmaf(a.z, wv[2].x, acc[r].x);
            acc[r].y = fmaf(a.z, wv[2].y, acc[r].y);
            acc[r].z = fmaf(a.z, wv[2].z, acc[r].z);
            acc[r].w = fmaf(a.z, wv[2].w, acc[r].w);
            acc[r].x = fmaf(a.w, wv[3].x, acc[r].x);
            acc[r].y = fmaf(a.w, wv[3].y, acc[r].y);
            acc[r].z = fmaf(a.w, wv[3].z, acc[r].z);
            acc[r].w = fmaf(a.w, wv[3].w, acc[r].w);
        }
    }
    #pragma unroll
    for (int r = 0; r < 4; r++) {
        int row = row0 + rc + r;
        if (row < N_NODES) *(float4*)&g_ha[row * 64 + jc] = acc[r];
    }
}

// fused layer: x_l = A_hat h_l + b_l (smem rows) ; mean(x_l) ; h_{l+1} = x_l W_{l+1}
__global__ void k_layer(int in_sel, int layer, int has_next,
                        const float4* __restrict__ b4,
                        const float* __restrict__ Wn) {
    const float4* h4   = (const float4*)(in_sel == 0 ? g_ha : g_hb);
    float*        hout = (in_sel == 0 ? g_hb : g_ha);

    __shared__ float rows[NPB * RSTRIDE];
    __shared__ float Ws[64 * 64];
    __shared__ float msum[4 * 64];

    int tid = threadIdx.x;
    if (has_next) {
        const float4* W4 = (const float4*)Wn;
        float4* Ws4 = (float4*)Ws;
        #pragma unroll
        for (int i = tid; i < 1024; i += 256) Ws4[i] = W4[i];
    }

    // ---- gather phase: 4 threads/node, 16 cols each ----
    int nl   = tid >> 2;
    int q    = tid & 3;
    int node = blockIdx.x * NPB + nl;

    float4 acc[4];
    if (node < N_NODES) {
        float di = g_dinv[node];
        float sl = di * di;
        #pragma unroll
        for (int i = 0; i < 4; i++) {
            float4 v = h4[node * 16 + q * 4 + i];
            acc[i] = make_float4(v.x * sl, v.y * sl, v.z * sl, v.w * sl);
        }
        int beg = g_rowptr[node] + g_blocksum[node >> 8];
        int end = (node == N_NODES - 1)
                    ? N_EDGES
                    : (g_rowptr[node + 1] + g_blocksum[(node + 1) >> 8]);
        for (int j = beg; j < end; j++) {
            int2 e = __ldg(&g_csr[j]);
            float n = __int_as_float(e.y);
            #pragma unroll
            for (int i = 0; i < 4; i++) {
                float4 v = __ldg(&h4[e.x * 16 + q * 4 + i]);
                acc[i].x += v.x * n; acc[i].y += v.y * n;
                acc[i].z += v.z * n; acc[i].w += v.w * n;
            }
        }
        #pragma unroll
        for (int i = 0; i < 4; i++) {
            float4 bv = __ldg(&b4[q * 4 + i]);
            acc[i].x += bv.x; acc[i].y += bv.y;
            acc[i].z += bv.z; acc[i].w += bv.w;
            *(float4*)&rows[nl * RSTRIDE + q * 16 + i * 4] = acc[i];
        }
    } else {
        #pragma unroll
        for (int i = 0; i < 4; i++)
            *(float4*)&rows[nl * RSTRIDE + q * 16 + i * 4] =
                make_float4(0.f, 0.f, 0.f, 0.f);
    }
    __syncthreads();

    // ---- mean phase ----
    {
        int c = tid & 63, grp = tid >> 6;
        float s = 0.f;
        #pragma unroll
        for (int i = 0; i < 16; i++) s += rows[(grp * 16 + i) * RSTRIDE + c];
        msum[grp * 64 + c] = s;
    }
    __syncthreads();
    if (tid < 64) {
        float tot = msum[tid] + msum[64 + tid] + msum[128 + tid] + msum[192 + tid];
        atomicAdd(&g_meanacc[(layer * MEAN_SPREAD + (blockIdx.x & (MEAN_SPREAD - 1))) * D + tid], tot);
    }

    // ---- GEMM phase ----
    if (has_next) {
        int jc = (tid & 15) * 4;
        int rc = (tid >> 4) * 4;
        float4 g[4];
        #pragma unroll
        for (int r = 0; r < 4; r++) g[r] = make_float4(0.f, 0.f, 0.f, 0.f);

        #pragma unroll
        for (int k4 = 0; k4 < 16; k4++) {
            float4 wv[4];
            #pragma unroll
            for (int kk = 0; kk < 4; kk++)
                wv[kk] = *(const float4*)&Ws[(k4 * 4 + kk) * 64 + jc];
            #pragma unroll
            for (int r = 0; r < 4; r++) {
                float4 a = *(const float4*)&rows[(rc + r) * RSTRIDE + k4 * 4];
                g[r].x = fmaf(a.x, wv[0].x, g[r].x);
                g[r].y = fmaf(a.x, wv[0].y, g[r].y);
                g[r].z = fmaf(a.x, wv[0].z, g[r].z);
                g[r].w = fmaf(a.x, wv[0].w, g[r].w);
                g[r].x = fmaf(a.y, wv[1].x, g[r].x);
                g[r].y = fmaf(a.y, wv[1].y, g[r].y);
                g[r].z = fmaf(a.y, wv[1].z, g[r].z);
                g[r].w = fmaf(a.y, wv[1].w, g[r].w);
                g[r].x = fmaf(a.z, wv[2].x, g[r].x);
                g[r].y = fmaf(a.z, wv[2].y, g[r].y);
                g[r].z = fmaf(a.z, wv[2].z, g[r].z);
                g[r].w = fmaf(a.z, wv[2].w, g[r].w);
                g[r].x = fmaf(a.w, wv[3].x, g[r].x);
                g[r].y = fmaf(a.w, wv[3].y, g[r].y);
                g[r].z = fmaf(a.w, wv[3].z, g[r].z);
                g[r].w = fmaf(a.w, wv[3].w, g[r].w);
            }
        }
        int row0 = blockIdx.x * NPB;
        #pragma unroll
        for (int r = 0; r < 4; r++) {
            int row = row0 + rc + r;
            if (row < N_NODES) *(float4*)&hout[row * 64 + jc] = g[r];
        }
    }
}

__global__ void k_finish(float* __restrict__ out) {
    if (blockIdx.x == 0) {
        int t = threadIdx.x;
        int layer = t >> 6, c = t & 63;
        float s = 0.f;
        #pragma unroll
        for (int k = 0; k < MEAN_SPREAD; k++)
            s += g_meanacc[(layer * MEAN_SPREAD + k) * D + c];
        out[layer * D + c] = s * (1.0f / (float)N_NODES);
        __syncthreads();
        for (int i = t; i < 4 * MEAN_SPREAD * D; i += 256) g_meanacc[i] = 0.f;
    }
    int i = blockIdx.x * blockDim.x + threadIdx.x;
    if (i < N_NODES) { g_cnt[i] = 0; g_cur[i] = 0; }
}

extern "C" void kernel_launch(void* const* d_in, const int* in_sizes, int n_in,
                              void* d_out, int out_size) {
    const float* x   = (const float*)d_in[0];
    const void*  ei  = d_in[1];
    float*       out = (float*)d_out;

    k_detect<<<1, 256>>>((const int*)ei);
    k_hist  <<<(N_EDGES + 255) / 256, 256>>>(ei);
    k_scan1 <<<SCAN_NBLK, SCAN_B>>>();
    k_scan2 <<<1, SCAN_B>>>();
    k_fill  <<<(N_EDGES + 255) / 256, 256>>>(ei);
    k_gemm0 <<<(N_NODES + 63) / 64, 256>>>(x, (const float*)d_in[2]);

    for (int l = 0; l < 4; l++) {
        int has_next = (l < 3);
        const float* bl = (const float*)d_in[3 + 2 * l];
        const float* Wn = has_next ? (const float*)d_in[2 + 2 * (l + 1)]
                                   : (const float*)d_in[2];   // unused when !has_next
        k_layer<<<LAYER_GRID, 256>>>(l & 1, l, has_next, (const float4*)bl, Wn);
    }
    k_finish<<<SCAN_NBLK, 256>>>(out);
}

// round 10
// speedup vs baseline: 1.2274x; 1.2274x over previous
#include <cuda_runtime.h>

#define N_NODES 50000
#define N_EDGES 800000
#define D 64
#define SCAN_B 256
#define SCAN_NBLK ((N_NODES + SCAN_B - 1) / SCAN_B)   // 196
#define MEAN_SPREAD 8

// ---------------- scratch (static device memory; zero at load & at graph end)
__device__ float g_h [N_NODES * D];   // h = x @ W (pre-aggregation)
__device__ float g_xa[N_NODES * D];   // ping
__device__ float g_xb[N_NODES * D];   // pong
__device__ float g_dinv[N_NODES];
__device__ int   g_cnt [N_NODES];     // in-degree histogram
__device__ int   g_cur [N_NODES];     // fill cursors
__device__ int   g_rowptr[N_NODES];   // block-local exclusive prefix
__device__ int   g_blocksum[SCAN_NBLK];
__device__ int2  g_csr[N_EDGES];      // dst-sorted (src, nrm-bits)
__device__ float g_meanacc[4 * MEAN_SPREAD * D];
__device__ int   g_is64;

__device__ __forceinline__ float* selbuf(int s) { return (s == 0) ? g_xa : g_xb; }

// ---------------- dtype detect: int64 indices < 50000 have zero high words --
__global__ void k_detect(const int* __restrict__ ei32) {
    __shared__ int bad;
    if (threadIdx.x == 0) bad = 0;
    __syncthreads();
    for (int t = threadIdx.x; t < 1024; t += blockDim.x)
        if (ei32[2 * t + 1] != 0) bad = 1;
    __syncthreads();
    if (threadIdx.x == 0) g_is64 = bad ? 0 : 1;
}

__device__ __forceinline__ int load_idx(const void* ei, int pos) {
    int v = g_is64 ? (int)((const long long*)ei)[pos] : ((const int*)ei)[pos];
    return min(max(v, 0), N_NODES - 1);
}

// ---------------- in-degree histogram (reads raw edge buffer) ---------------
__global__ void k_hist(const void* __restrict__ ei) {
    int e = blockIdx.x * blockDim.x + threadIdx.x;
    if (e < N_EDGES) atomicAdd(&g_cnt[load_idx(ei, N_EDGES + e)], 1);
}

// ---------------- scan stage 1 (+ dinv fused) ----------------
__global__ void k_scan1() {
    __shared__ int sh[SCAN_B];
    int b = blockIdx.x, t = threadIdx.x;
    int i = b * SCAN_B + t;
    int v = (i < N_NODES) ? g_cnt[i] : 0;
    sh[t] = v;
    __syncthreads();
    for (int off = 1; off < SCAN_B; off <<= 1) {
        int add = (t >= off) ? sh[t - off] : 0;
        __syncthreads();
        sh[t] += add;
        __syncthreads();
    }
    if (i < N_NODES) {
        g_rowptr[i] = sh[t] - v;                 // block-local exclusive
        g_dinv[i]   = rsqrtf(1.0f + (float)v);   // +1 self-loop
    }
    if (t == SCAN_B - 1) g_blocksum[b] = sh[t];
}

// ---------------- scan stage 2: exclusive scan of block sums ----------------
__global__ void k_scan2() {
    __shared__ int sh[SCAN_B];
    int t = threadIdx.x;
    int v = (t < SCAN_NBLK) ? g_blocksum[t] : 0;
    sh[t] = v;
    __syncthreads();
    for (int off = 1; off < SCAN_B; off <<= 1) {
        int add = (t >= off) ? sh[t - off] : 0;
        __syncthreads();
        sh[t] += add;
        __syncthreads();
    }
    if (t < SCAN_NBLK) g_blocksum[t] = sh[t] - v;
}

// ---------------- CSR fill: dst-sorted packed (src, norm) -------------------
__global__ void k_fill(const void* __restrict__ ei) {
    int e = blockIdx.x * blockDim.x + threadIdx.x;
    if (e >= N_EDGES) return;
    int s = load_idx(ei, e);
    int d = load_idx(ei, N_EDGES + e);
    int pos = g_rowptr[d] + g_blocksum[d >> 8] + atomicAdd(&g_cur[d], 1);
    g_csr[pos] = make_int2(s, __float_as_int(g_dinv[s] * g_dinv[d]));
}

// ---------------- GEMM: h = xin @ W (64 rows/block, 4x4 register tile) ------
__global__ void k_gemm(int in_sel,
                       const float* __restrict__ x0,
                       const float* __restrict__ W) {
    const float* xin = (in_sel < 0) ? x0 : (const float*)selbuf(in_sel);

    __shared__ float Ws[64 * 64];
    __shared__ float xs[64 * 64];

    int tid = threadIdx.x;
    const float4* W4 = (const float4*)W;
    float4* Ws4 = (float4*)Ws;
    #pragma unroll
    for (int i = tid; i < 1024; i += 256) Ws4[i] = W4[i];

    int row0 = blockIdx.x * 64;
    const float4* x4 = (const float4*)xin;
    float4* xs4 = (float4*)xs;
    #pragma unroll
    for (int i = tid; i < 1024; i += 256) {
        int r = row0 + (i >> 4);
        xs4[i] = (r < N_NODES) ? x4[r * 16 + (i & 15)]
                               : make_float4(0.f, 0.f, 0.f, 0.f);
    }
    __syncthreads();

    int jc = (tid & 15) * 4;    // 4 output columns
    int rc = (tid >> 4) * 4;    // 4 rows

    float4 acc[4];
    #pragma unroll
    for (int r = 0; r < 4; r++) acc[r] = make_float4(0.f, 0.f, 0.f, 0.f);

    #pragma unroll
    for (int k4 = 0; k4 < 16; k4++) {
        float4 wv[4];
        #pragma unroll
        for (int kk = 0; kk < 4; kk++)
            wv[kk] = *(const float4*)&Ws[(k4 * 4 + kk) * 64 + jc];
        #pragma unroll
        for (int r = 0; r < 4; r++) {
            float4 a = *(const float4*)&xs[(rc + r) * 64 + k4 * 4];
            acc[r].x = fmaf(a.x, wv[0].x, acc[r].x);
            acc[r].y = fmaf(a.x, wv[0].y, acc[r].y);
            acc[r].z = fmaf(a.x, wv[0].z, acc[r].z);
            acc[r].w = fmaf(a.x, wv[0].w, acc[r].w);
            acc[r].x = fmaf(a.y, wv[1].x, acc[r].x);
            acc[r].y = fmaf(a.y, wv[1].y, acc[r].y);
            acc[r].z = fmaf(a.y, wv[1].z, acc[r].z);
            acc[r].w = fmaf(a.y, wv[1].w, acc[r].w);
            acc[r].x = fmaf(a.z, wv[2].x, acc[r].x);
            acc[r].y = fmaf(a.z, wv[2].y, acc[r].y);
            acc[r].z = fmaf(a.z, wv[2].z, acc[r].z);
            acc[r].w = fmaf(a.z, wv[2].w, acc[r].w);
            acc[r].x = fmaf(a.w, wv[3].x, acc[r].x);
            acc[r].y = fmaf(a.w, wv[3].y, acc[r].y);
            acc[r].z = fmaf(a.w, wv[3].z, acc[r].z);
            acc[r].w = fmaf(a.w, wv[3].w, acc[r].w);
        }
    }
    #pragma unroll
    for (int r = 0; r < 4; r++) {
        int row = row0 + rc + r;
        if (row < N_NODES) *(float4*)&g_h[row * 64 + jc] = acc[r];
    }
}

// ---------------- pull aggregation + fused mean ------------------------------
// 16 threads/node, float4 columns; warp covers 2 nodes (loop to warp-max len).
// 4x unrolled gather for MLP.
__global__ void k_aggr(int out_sel, int layer, const float4* __restrict__ b4p) {
    int id   = blockIdx.x * 256 + threadIdx.x;
    int node = id >> 4;
    int c4   = id & 15;
    const float4* h4   = (const float4*)g_h;
    float4*       out4 = (float4*)selbuf(out_sel);

    float di = g_dinv[node];
    float sl = di * di;
    float4 acc = h4[node * 16 + c4];          // self-loop message
    acc.x *= sl; acc.y *= sl; acc.z *= sl; acc.w *= sl;

    int beg = g_rowptr[node] + g_blocksum[node >> 8];
    int end = (node == N_NODES - 1)
                ? N_EDGES
                : (g_rowptr[node + 1] + g_blocksum[(node + 1) >> 8]);
    int len = end - beg;
    int m   = max(len, __shfl_xor_sync(0xffffffffu, len, 16));

    for (int j = 0; j < m; j += 4) {
        int2   e[4];
        float4 v[4];
        bool   p[4];
        #pragma unroll
        for (int u = 0; u < 4; u++) {
            p[u] = (j + u < len);
            if (p[u]) e[u] = __ldg(&g_csr[beg + j + u]);
        }
        #pragma unroll
        for (int u = 0; u < 4; u++)
            if (p[u]) v[u] = __ldg(&h4[e[u].x * 16 + c4]);
        #pragma unroll
        for (int u = 0; u < 4; u++) {
            if (p[u]) {
                float n = __int_as_float(e[u].y);
                acc.x += v[u].x * n; acc.y += v[u].y * n;
                acc.z += v[u].z * n; acc.w += v[u].w * n;
            }
        }
    }
    float4 bv = __ldg(&b4p[c4]);
    acc.x += bv.x; acc.y += bv.y; acc.z += bv.z; acc.w += bv.w;
    out4[node * 16 + c4] = acc;

    // fused column-mean: block reduce 16 nodes, spread-atomic to scratch
    __shared__ float4 sh[256];
    int t = threadIdx.x;
    sh[t] = acc;
    __syncthreads();
    if (t < 128) { sh[t].x += sh[t+128].x; sh[t].y += sh[t+128].y;
                   sh[t].z += sh[t+128].z; sh[t].w += sh[t+128].w; }
    __syncthreads();
    if (t < 64)  { sh[t].x += sh[t+64].x; sh[t].y += sh[t+64].y;
                   sh[t].z += sh[t+64].z; sh[t].w += sh[t+64].w; }
    __syncthreads();
    if (t < 32)  { sh[t].x += sh[t+32].x; sh[t].y += sh[t+32].y;
                   sh[t].z += sh[t+32].z; sh[t].w += sh[t+32].w; }
    __syncthreads();
    if (t < 16) {
        float4 s = sh[t];
        s.x += sh[t+16].x; s.y += sh[t+16].y; s.z += sh[t+16].z; s.w += sh[t+16].w;
        float* gp = &g_meanacc[(layer * MEAN_SPREAD + (blockIdx.x & (MEAN_SPREAD - 1))) * D + t * 4];
        atomicAdd(&gp[0], s.x);
        atomicAdd(&gp[1], s.y);
        atomicAdd(&gp[2], s.z);
        atomicAdd(&gp[3], s.w);
    }
}

// ---------------- finish: write d_out; restore zero invariants --------------
__global__ void k_finish(float* __restrict__ out) {
    if (blockIdx.x == 0) {
        int t = threadIdx.x;              // 256: layer = t>>6, col = t&63
        int layer = t >> 6, c = t & 63;
        float s = 0.f;
        #pragma unroll
        for (int k = 0; k < MEAN_SPREAD; k++)
            s += g_meanacc[(layer * MEAN_SPREAD + k) * D + c];
        out[layer * D + c] = s * (1.0f / (float)N_NODES);
        __syncthreads();                  // all reads done before zeroing
        for (int i = t; i < 4 * MEAN_SPREAD * D; i += 256) g_meanacc[i] = 0.f;
    }
    int i = blockIdx.x * blockDim.x + threadIdx.x;
    if (i < N_NODES) { g_cnt[i] = 0; g_cur[i] = 0; }
}

// ---------------- launch ----------------
extern "C" void kernel_launch(void* const* d_in, const int* in_sizes, int n_in,
                              void* d_out, int out_size) {
    const float* x   = (const float*)d_in[0];
    const void*  ei  = d_in[1];
    float*       out = (float*)d_out;

    k_detect<<<1, 256>>>((const int*)ei);
    k_hist  <<<(N_EDGES + 255) / 256, 256>>>(ei);
    k_scan1 <<<SCAN_NBLK, SCAN_B>>>();
    k_scan2 <<<1, SCAN_B>>>();
    k_fill  <<<(N_EDGES + 255) / 256, 256>>>(ei);

    for (int l = 0; l < 4; l++) {
        int in_sel  = (l == 0) ? -1 : ((l - 1) & 1);
        int out_sel = l & 1;
        const float* W = (const float*)d_in[2 + 2 * l];
        const float* b = (const float*)d_in[3 + 2 * l];
        k_gemm<<<(N_NODES + 63) / 64, 256>>>(in_sel, x, W);
        k_aggr<<<(N_NODES * 16) / 256, 256>>>(out_sel, l, (const float4*)b);
    }
    k_finish<<<SCAN_NBLK, 256>>>(out);
}

// round 11
// speedup vs baseline: 1.2400x; 1.0103x over previous
#include <cuda_runtime.h>

#define N_NODES 50000
#define N_EDGES 800000
#define D 64
#define SCAN_B 256
#define SCAN_NBLK ((N_NODES + SCAN_B - 1) / SCAN_B)   // 196
#define MEAN_SPREAD 8

// ---------------- scratch (static device memory; zero at load & at graph end)
__device__ float g_h [N_NODES * D];   // hs = (x @ W) * dinv[row]
__device__ float g_xa[N_NODES * D];   // ping
__device__ float g_xb[N_NODES * D];   // pong
__device__ float g_dinv[N_NODES];
__device__ int   g_cnt [N_NODES];     // in-degree histogram
__device__ int   g_cur [N_NODES];     // fill cursors
__device__ int   g_rowptr[N_NODES];   // block-local exclusive prefix
__device__ int   g_blocksum[SCAN_NBLK];
__device__ int   g_csr[N_EDGES];      // dst-sorted sources (norm factored out!)
__device__ float g_meanacc[4 * MEAN_SPREAD * D];
__device__ int   g_is64;

__device__ __forceinline__ float* selbuf(int s) { return (s == 0) ? g_xa : g_xb; }

// ---------------- dtype detect: int64 indices < 50000 have zero high words --
__global__ void k_detect(const int* __restrict__ ei32) {
    __shared__ int bad;
    if (threadIdx.x == 0) bad = 0;
    __syncthreads();
    for (int t = threadIdx.x; t < 1024; t += blockDim.x)
        if (ei32[2 * t + 1] != 0) bad = 1;
    __syncthreads();
    if (threadIdx.x == 0) g_is64 = bad ? 0 : 1;
}

__device__ __forceinline__ int load_idx(const void* ei, int pos) {
    int v = g_is64 ? (int)((const long long*)ei)[pos] : ((const int*)ei)[pos];
    return min(max(v, 0), N_NODES - 1);
}

// ---------------- in-degree histogram (reads raw edge buffer) ---------------
__global__ void k_hist(const void* __restrict__ ei) {
    int e = blockIdx.x * blockDim.x + threadIdx.x;
    if (e < N_EDGES) atomicAdd(&g_cnt[load_idx(ei, N_EDGES + e)], 1);
}

// ---------------- scan stage 1 (+ dinv fused) ----------------
__global__ void k_scan1() {
    __shared__ int sh[SCAN_B];
    int b = blockIdx.x, t = threadIdx.x;
    int i = b * SCAN_B + t;
    int v = (i < N_NODES) ? g_cnt[i] : 0;
    sh[t] = v;
    __syncthreads();
    for (int off = 1; off < SCAN_B; off <<= 1) {
        int add = (t >= off) ? sh[t - off] : 0;
        __syncthreads();
        sh[t] += add;
        __syncthreads();
    }
    if (i < N_NODES) {
        g_rowptr[i] = sh[t] - v;                 // block-local exclusive
        g_dinv[i]   = rsqrtf(1.0f + (float)v);   // +1 self-loop
    }
    if (t == SCAN_B - 1) g_blocksum[b] = sh[t];
}

// ---------------- scan stage 2: exclusive scan of block sums ----------------
__global__ void k_scan2() {
    __shared__ int sh[SCAN_B];
    int t = threadIdx.x;
    int v = (t < SCAN_NBLK) ? g_blocksum[t] : 0;
    sh[t] = v;
    __syncthreads();
    for (int off = 1; off < SCAN_B; off <<= 1) {
        int add = (t >= off) ? sh[t - off] : 0;
        __syncthreads();
        sh[t] += add;
        __syncthreads();
    }
    if (t < SCAN_NBLK) g_blocksum[t] = sh[t] - v;
}

// ---------------- CSR fill: dst-sorted src only ------------------------------
__global__ void k_fill(const void* __restrict__ ei) {
    int e = blockIdx.x * blockDim.x + threadIdx.x;
    if (e >= N_EDGES) return;
    int s = load_idx(ei, e);
    int d = load_idx(ei, N_EDGES + e);
    int pos = g_rowptr[d] + g_blocksum[d >> 8] + atomicAdd(&g_cur[d], 1);
    g_csr[pos] = s;
}

// ---------------- GEMM: hs = (xin @ W) * dinv[row] ---------------------------
__global__ void k_gemm(int in_sel,
                       const float* __restrict__ x0,
                       const float* __restrict__ W) {
    const float* xin = (in_sel < 0) ? x0 : (const float*)selbuf(in_sel);

    __shared__ float Ws[64 * 64];
    __shared__ float xs[64 * 64];

    int tid = threadIdx.x;
    const float4* W4 = (const float4*)W;
    float4* Ws4 = (float4*)Ws;
    #pragma unroll
    for (int i = tid; i < 1024; i += 256) Ws4[i] = W4[i];

    int row0 = blockIdx.x * 64;
    const float4* x4 = (const float4*)xin;
    float4* xs4 = (float4*)xs;
    #pragma unroll
    for (int i = tid; i < 1024; i += 256) {
        int r = row0 + (i >> 4);
        xs4[i] = (r < N_NODES) ? x4[r * 16 + (i & 15)]
                               : make_float4(0.f, 0.f, 0.f, 0.f);
    }
    __syncthreads();

    int jc = (tid & 15) * 4;    // 4 output columns
    int rc = (tid >> 4) * 4;    // 4 rows

    float4 acc[4];
    #pragma unroll
    for (int r = 0; r < 4; r++) acc[r] = make_float4(0.f, 0.f, 0.f, 0.f);

    #pragma unroll
    for (int k4 = 0; k4 < 16; k4++) {
        float4 wv[4];
        #pragma unroll
        for (int kk = 0; kk < 4; kk++)
            wv[kk] = *(const float4*)&Ws[(k4 * 4 + kk) * 64 + jc];
        #pragma unroll
        for (int r = 0; r < 4; r++) {
            float4 a = *(const float4*)&xs[(rc + r) * 64 + k4 * 4];
            acc[r].x = fmaf(a.x, wv[0].x, acc[r].x);
            acc[r].y = fmaf(a.x, wv[0].y, acc[r].y);
            acc[r].z = fmaf(a.x, wv[0].z, acc[r].z);
            acc[r].w = fmaf(a.x, wv[0].w, acc[r].w);
            acc[r].x = fmaf(a.y, wv[1].x, acc[r].x);
            acc[r].y = fmaf(a.y, wv[1].y, acc[r].y);
            acc[r].z = fmaf(a.y, wv[1].z, acc[r].z);
            acc[r].w = fmaf(a.y, wv[1].w, acc[r].w);
            acc[r].x = fmaf(a.z, wv[2].x, acc[r].x);
            acc[r].y = fmaf(a.z, wv[2].y, acc[r].y);
            acc[r].z = fmaf(a.z, wv[2].z, acc[r].z);
            acc[r].w = fmaf(a.z, wv[2].w, acc[r].w);
            acc[r].x = fmaf(a.w, wv[3].x, acc[r].x);
            acc[r].y = fmaf(a.w, wv[3].y, acc[r].y);
            acc[r].z = fmaf(a.w, wv[3].z, acc[r].z);
            acc[r].w = fmaf(a.w, wv[3].w, acc[r].w);
        }
    }
    #pragma unroll
    for (int r = 0; r < 4; r++) {
        int row = row0 + rc + r;
        if (row < N_NODES) {
            float di = g_dinv[row];
            acc[r].x *= di; acc[r].y *= di; acc[r].z *= di; acc[r].w *= di;
            *(float4*)&g_h[row * 64 + jc] = acc[r];
        }
    }
}

// ---------------- pull aggregation + fused mean ------------------------------
// out[d] = dinv[d] * (sum_in hs[s] + hs[d]) + b.  16 threads/node; warp covers
// 2 nodes (loop to warp-max len); 4x unrolled pure-FADD gather.
__global__ void k_aggr(int out_sel, int layer, const float4* __restrict__ b4p) {
    int id   = blockIdx.x * 256 + threadIdx.x;
    int node = id >> 4;
    int c4   = id & 15;
    const float4* h4   = (const float4*)g_h;
    float4*       out4 = (float4*)selbuf(out_sel);

    float4 acc = h4[node * 16 + c4];          // hs[d] (self-loop term)

    int beg = g_rowptr[node] + g_blocksum[node >> 8];
    int end = (node == N_NODES - 1)
                ? N_EDGES
                : (g_rowptr[node + 1] + g_blocksum[(node + 1) >> 8]);
    int len = end - beg;
    int m   = max(len, __shfl_xor_sync(0xffffffffu, len, 16));

    for (int j = 0; j < m; j += 4) {
        int    s[4];
        float4 v[4];
        bool   p[4];
        #pragma unroll
        for (int u = 0; u < 4; u++) {
            p[u] = (j + u < len);
            if (p[u]) s[u] = __ldg(&g_csr[beg + j + u]);
        }
        #pragma unroll
        for (int u = 0; u < 4; u++)
            if (p[u]) v[u] = __ldg(&h4[s[u] * 16 + c4]);
        #pragma unroll
        for (int u = 0; u < 4; u++) {
            if (p[u]) {
                acc.x += v[u].x; acc.y += v[u].y;
                acc.z += v[u].z; acc.w += v[u].w;
            }
        }
    }
    float dd = g_dinv[node];
    float4 bv = __ldg(&b4p[c4]);
    acc.x = fmaf(acc.x, dd, bv.x);
    acc.y = fmaf(acc.y, dd, bv.y);
    acc.z = fmaf(acc.z, dd, bv.z);
    acc.w = fmaf(acc.w, dd, bv.w);
    out4[node * 16 + c4] = acc;

    // fused column-mean: block reduce 16 nodes, spread-atomic to scratch
    __shared__ float4 sh[256];
    int t = threadIdx.x;
    sh[t] = acc;
    __syncthreads();
    if (t < 128) { sh[t].x += sh[t+128].x; sh[t].y += sh[t+128].y;
                   sh[t].z += sh[t+128].z; sh[t].w += sh[t+128].w; }
    __syncthreads();
    if (t < 64)  { sh[t].x += sh[t+64].x; sh[t].y += sh[t+64].y;
                   sh[t].z += sh[t+64].z; sh[t].w += sh[t+64].w; }
    __syncthreads();
    if (t < 32)  { sh[t].x += sh[t+32].x; sh[t].y += sh[t+32].y;
                   sh[t].z += sh[t+32].z; sh[t].w += sh[t+32].w; }
    __syncthreads();
    if (t < 16) {
        float4 s = sh[t];
        s.x += sh[t+16].x; s.y += sh[t+16].y; s.z += sh[t+16].z; s.w += sh[t+16].w;
        float* gp = &g_meanacc[(layer * MEAN_SPREAD + (blockIdx.x & (MEAN_SPREAD - 1))) * D + t * 4];
        atomicAdd(&gp[0], s.x);
        atomicAdd(&gp[1], s.y);
        atomicAdd(&gp[2], s.z);
        atomicAdd(&gp[3], s.w);
    }
}

// ---------------- finish: write d_out; restore zero invariants --------------
__global__ void k_finish(float* __restrict__ out) {
    if (blockIdx.x == 0) {
        int t = threadIdx.x;              // 256: layer = t>>6, col = t&63
        int layer = t >> 6, c = t & 63;
        float s = 0.f;
        #pragma unroll
        for (int k = 0; k < MEAN_SPREAD; k++)
            s += g_meanacc[(layer * MEAN_SPREAD + k) * D + c];
        out[layer * D + c] = s * (1.0f / (float)N_NODES);
        __syncthreads();                  // all reads done before zeroing
        for (int i = t; i < 4 * MEAN_SPREAD * D; i += 256) g_meanacc[i] = 0.f;
    }
    int i = blockIdx.x * blockDim.x + threadIdx.x;
    if (i < N_NODES) { g_cnt[i] = 0; g_cur[i] = 0; }
}

// ---------------- launch ----------------
extern "C" void kernel_launch(void* const* d_in, const int* in_sizes, int n_in,
                              void* d_out, int out_size) {
    const float* x   = (const float*)d_in[0];
    const void*  ei  = d_in[1];
    float*       out = (float*)d_out;

    k_detect<<<1, 256>>>((const int*)ei);
    k_hist  <<<(N_EDGES + 255) / 256, 256>>>(ei);
    k_scan1 <<<SCAN_NBLK, SCAN_B>>>();
    k_scan2 <<<1, SCAN_B>>>();
    k_fill  <<<(N_EDGES + 255) / 256, 256>>>(ei);

    for (int l = 0; l < 4; l++) {
        int in_sel  = (l == 0) ? -1 : ((l - 1) & 1);
        int out_sel = l & 1;
        const float* W = (const float*)d_in[2 + 2 * l];
        const float* b = (const float*)d_in[3 + 2 * l];
        k_gemm<<<(N_NODES + 63) / 64, 256>>>(in_sel, x, W);
        k_aggr<<<(N_NODES * 16) / 256, 256>>>(out_sel, l, (const float4*)b);
    }
    k_finish<<<SCAN_NBLK, 256>>>(out);
}

// round 12
// speedup vs baseline: 1.4079x; 1.1354x over previous
#include <cuda_runtime.h>

#define N_NODES 50000
#define N_EDGES 800000
#define D 64
#define SCAN_B 256
#define SCAN_NBLK ((N_NODES + SCAN_B - 1) / SCAN_B)   // 196
#define MEAN_SPREAD 8

// ---------------- scratch (static device memory; zero at load & at graph end)
__device__ float g_h [N_NODES * D];   // hs = (x @ W) * dinv[row]
__device__ float g_xa[N_NODES * D];   // ping
__device__ float g_xb[N_NODES * D];   // pong
__device__ float g_dinv[N_NODES];
__device__ int   g_cnt [N_NODES];     // in-degree histogram
__device__ int   g_cur [N_NODES];     // fill cursors
__device__ int   g_rowptr[N_NODES];   // block-local exclusive prefix
__device__ int   g_blocksum[SCAN_NBLK];
__device__ int   g_csr[N_EDGES];      // dst-sorted sources (norm factored out)
__device__ float g_meanacc[4 * MEAN_SPREAD * D];
__device__ int   g_scanctr;           // last-block-done counter (self-resetting)

__device__ __forceinline__ float* selbuf(int s) { return (s == 0) ? g_xa : g_xb; }

// int64 indices < 50000 have zero high words at odd int32 positions.
// For int32 random indices, 8 words all zero has P ~ (2e-5)^8 ~ 0.
__device__ __forceinline__ int detect64(const int* __restrict__ p32) {
    return ((p32[1] | p32[3] | p32[5] | p32[7] |
             p32[9] | p32[11] | p32[13] | p32[15]) == 0);
}

__device__ __forceinline__ int load_idx(const void* ei, int pos, int is64) {
    int v = is64 ? (int)((const long long*)ei)[pos] : ((const int*)ei)[pos];
    return min(max(v, 0), N_NODES - 1);
}

// ---------------- in-degree histogram (reads raw edge buffer) ---------------
__global__ void k_hist(const void* __restrict__ ei) {
    __shared__ int s_is64;
    if (threadIdx.x == 0) s_is64 = detect64((const int*)ei);
    __syncthreads();
    int e = blockIdx.x * blockDim.x + threadIdx.x;
    if (e < N_EDGES) atomicAdd(&g_cnt[load_idx(ei, N_EDGES + e, s_is64)], 1);
}

// ---------------- scan (both stages fused; + dinv) ---------------------------
__global__ void k_scan() {
    __shared__ int sh[SCAN_B];
    __shared__ int isLast;
    int b = blockIdx.x, t = threadIdx.x;
    int i = b * SCAN_B + t;
    int v = (i < N_NODES) ? g_cnt[i] : 0;
    sh[t] = v;
    __syncthreads();
    for (int off = 1; off < SCAN_B; off <<= 1) {
        int add = (t >= off) ? sh[t - off] : 0;
        __syncthreads();
        sh[t] += add;
        __syncthreads();
    }
    if (i < N_NODES) {
        g_rowptr[i] = sh[t] - v;                 // block-local exclusive
        g_dinv[i]   = rsqrtf(1.0f + (float)v);   // +1 self-loop
    }
    if (t == SCAN_B - 1) g_blocksum[b] = sh[t];
    __threadfence();
    if (t == 0) isLast = (atomicAdd(&g_scanctr, 1) == (int)gridDim.x - 1);
    __syncthreads();

    if (isLast) {   // last finishing block scans the block sums (196 <= 256)
        int w = (t < SCAN_NBLK) ? g_blocksum[t] : 0;
        sh[t] = w;
        __syncthreads();
        for (int off = 1; off < SCAN_B; off <<= 1) {
            int add = (t >= off) ? sh[t - off] : 0;
            __syncthreads();
            sh[t] += add;
            __syncthreads();
        }
        if (t < SCAN_NBLK) g_blocksum[t] = sh[t] - w;   // exclusive
        if (t == 0) g_scanctr = 0;                      // restore invariant
    }
}

// ---------------- CSR fill: dst-sorted src only ------------------------------
__global__ void k_fill(const void* __restrict__ ei) {
    __shared__ int s_is64;
    if (threadIdx.x == 0) s_is64 = detect64((const int*)ei);
    __syncthreads();
    int e = blockIdx.x * blockDim.x + threadIdx.x;
    if (e >= N_EDGES) return;
    int s = load_idx(ei, e, s_is64);
    int d = load_idx(ei, N_EDGES + e, s_is64);
    int pos = g_rowptr[d] + g_blocksum[d >> 8] + atomicAdd(&g_cur[d], 1);
    g_csr[pos] = s;
}

// ---------------- GEMM: hs = (xin @ W) * dinv[row] ---------------------------
__global__ void k_gemm(int in_sel,
                       const float* __restrict__ x0,
                       const float* __restrict__ W) {
    const float* xin = (in_sel < 0) ? x0 : (const float*)selbuf(in_sel);

    __shared__ float Ws[64 * 64];
    __shared__ float xs[64 * 64];

    int tid = threadIdx.x;
    const float4* W4 = (const float4*)W;
    float4* Ws4 = (float4*)Ws;
    #pragma unroll
    for (int i = tid; i < 1024; i += 256) Ws4[i] = W4[i];

    int row0 = blockIdx.x * 64;
    const float4* x4 = (const float4*)xin;
    float4* xs4 = (float4*)xs;
    #pragma unroll
    for (int i = tid; i < 1024; i += 256) {
        int r = row0 + (i >> 4);
        xs4[i] = (r < N_NODES) ? x4[r * 16 + (i & 15)]
                               : make_float4(0.f, 0.f, 0.f, 0.f);
    }
    __syncthreads();

    int jc = (tid & 15) * 4;    // 4 output columns
    int rc = (tid >> 4) * 4;    // 4 rows

    float4 acc[4];
    #pragma unroll
    for (int r = 0; r < 4; r++) acc[r] = make_float4(0.f, 0.f, 0.f, 0.f);

    #pragma unroll
    for (int k4 = 0; k4 < 16; k4++) {
        float4 wv[4];
        #pragma unroll
        for (int kk = 0; kk < 4; kk++)
            wv[kk] = *(const float4*)&Ws[(k4 * 4 + kk) * 64 + jc];
        #pragma unroll
        for (int r = 0; r < 4; r++) {
            float4 a = *(const float4*)&xs[(rc + r) * 64 + k4 * 4];
            acc[r].x = fmaf(a.x, wv[0].x, acc[r].x);
            acc[r].y = fmaf(a.x, wv[0].y, acc[r].y);
            acc[r].z = fmaf(a.x, wv[0].z, acc[r].z);
            acc[r].w = fmaf(a.x, wv[0].w, acc[r].w);
            acc[r].x = fmaf(a.y, wv[1].x, acc[r].x);
            acc[r].y = fmaf(a.y, wv[1].y, acc[r].y);
            acc[r].z = fmaf(a.y, wv[1].z, acc[r].z);
            acc[r].w = fmaf(a.y, wv[1].w, acc[r].w);
            acc[r].x = fmaf(a.z, wv[2].x, acc[r].x);
            acc[r].y = fmaf(a.z, wv[2].y, acc[r].y);
            acc[r].z = fmaf(a.z, wv[2].z, acc[r].z);
            acc[r].w = fmaf(a.z, wv[2].w, acc[r].w);
            acc[r].x = fmaf(a.w, wv[3].x, acc[r].x);
            acc[r].y = fmaf(a.w, wv[3].y, acc[r].y);
            acc[r].z = fmaf(a.w, wv[3].z, acc[r].z);
            acc[r].w = fmaf(a.w, wv[3].w, acc[r].w);
        }
    }
    #pragma unroll
    for (int r = 0; r < 4; r++) {
        int row = row0 + rc + r;
        if (row < N_NODES) {
            float di = g_dinv[row];
            acc[r].x *= di; acc[r].y *= di; acc[r].z *= di; acc[r].w *= di;
            *(float4*)&g_h[row * 64 + jc] = acc[r];
        }
    }
}

// ---------------- pull aggregation + fused mean (warp per node) --------------
// out[d] = dinv[d]*(sum_in hs[s] + hs[d]) + b. Two 16-lane groups split
// even/odd edges; combine with shfl_down(16). No padded iterations.
__global__ void k_aggr(int out_sel, int layer, const float4* __restrict__ b4p) {
    int tid  = threadIdx.x;
    int warp = tid >> 5;          // 8 warps = 8 nodes per block
    int lane = tid & 31;
    int half = lane >> 4;         // edge-parity group
    int c4   = lane & 15;         // float4 column
    int node = blockIdx.x * 8 + warp;   // grid = 6250, exact

    const float4* h4 = (const float4*)g_h;

    float4 acc = make_float4(0.f, 0.f, 0.f, 0.f);
    if (half == 0) acc = h4[node * 16 + c4];       // self-loop term hs[d]

    int beg = g_rowptr[node] + g_blocksum[node >> 8];
    int end = (node == N_NODES - 1)
                ? N_EDGES
                : (g_rowptr[node + 1] + g_blocksum[(node + 1) >> 8]);
    int len = end - beg;

    for (int j = half; j < len; j += 8) {          // this group's edges: j, j+2, j+4, j+6
        int    s[4];
        float4 v[4];
        bool   p[4];
        #pragma unroll
        for (int u = 0; u < 4; u++) {
            int jj = j + 2 * u;
            p[u] = (jj < len);
            if (p[u]) s[u] = __ldg(&g_csr[beg + jj]);
        }
        #pragma unroll
        for (int u = 0; u < 4; u++)
            if (p[u]) v[u] = __ldg(&h4[s[u] * 16 + c4]);
        #pragma unroll
        for (int u = 0; u < 4; u++) {
            if (p[u]) {
                acc.x += v[u].x; acc.y += v[u].y;
                acc.z += v[u].z; acc.w += v[u].w;
            }
        }
    }

    // combine the two halves
    acc.x += __shfl_down_sync(0xffffffffu, acc.x, 16);
    acc.y += __shfl_down_sync(0xffffffffu, acc.y, 16);
    acc.z += __shfl_down_sync(0xffffffffu, acc.z, 16);
    acc.w += __shfl_down_sync(0xffffffffu, acc.w, 16);

    __shared__ float4 sh4[8 * 16];
    if (half == 0) {
        float dd = g_dinv[node];
        float4 bv = __ldg(&b4p[c4]);
        float4 row;
        row.x = fmaf(acc.x, dd, bv.x);
        row.y = fmaf(acc.y, dd, bv.y);
        row.z = fmaf(acc.z, dd, bv.z);
        row.w = fmaf(acc.w, dd, bv.w);
        ((float4*)selbuf(out_sel))[node * 16 + c4] = row;
        sh4[warp * 16 + c4] = row;
    }
    __syncthreads();

    // fused column-mean: 8 rows in smem -> 64 partials -> spread atomics
    if (tid < 64) {
        const float* shf = (const float*)sh4;
        float s = 0.f;
        #pragma unroll
        for (int w = 0; w < 8; w++) s += shf[w * 64 + tid];
        atomicAdd(&g_meanacc[(layer * MEAN_SPREAD + (blockIdx.x & (MEAN_SPREAD - 1))) * D + tid], s);
    }
}

// ---------------- finish: write d_out; restore zero invariants --------------
__global__ void k_finish(float* __restrict__ out) {
    if (blockIdx.x == 0) {
        int t = threadIdx.x;              // 256: layer = t>>6, col = t&63
        int layer = t >> 6, c = t & 63;
        float s = 0.f;
        #pragma unroll
        for (int k = 0; k < MEAN_SPREAD; k++)
            s += g_meanacc[(layer * MEAN_SPREAD + k) * D + c];
        out[layer * D + c] = s * (1.0f / (float)N_NODES);
        __syncthreads();                  // all reads done before zeroing
        for (int i = t; i < 4 * MEAN_SPREAD * D; i += 256) g_meanacc[i] = 0.f;
    }
    int i = blockIdx.x * blockDim.x + threadIdx.x;
    if (i < N_NODES) { g_cnt[i] = 0; g_cur[i] = 0; }
}

// ---------------- launch ----------------
extern "C" void kernel_launch(void* const* d_in, const int* in_sizes, int n_in,
                              void* d_out, int out_size) {
    const float* x   = (const float*)d_in[0];
    const void*  ei  = d_in[1];
    float*       out = (float*)d_out;

    k_hist<<<(N_EDGES + 255) / 256, 256>>>(ei);
    k_scan<<<SCAN_NBLK, SCAN_B>>>();
    k_fill<<<(N_EDGES + 255) / 256, 256>>>(ei);

    for (int l = 0; l < 4; l++) {
        int in_sel  = (l == 0) ? -1 : ((l - 1) & 1);
        int out_sel = l & 1;
        const float* W = (const float*)d_in[2 + 2 * l];
        const float* b = (const float*)d_in[3 + 2 * l];
        k_gemm<<<(N_NODES + 63) / 64, 256>>>(in_sel, x, W);
        k_aggr<<<N_NODES / 8, 256>>>(out_sel, l, (const float4*)b);
    }
    k_finish<<<SCAN_NBLK, 256>>>(out);
}